// round 5
// baseline (speedup 1.0000x reference)
#include <cuda_runtime.h>
#include <cuda_bf16.h>
#include <cstdint>

// q,k,v: [2,12,2048,64] f32; mask: [2,1,1,2048] i32; bias: [1,12,2048,2048] f32
// out region: out [2,12,2048,64] then attn [2,12,2048,2048]
// attn = softmax((q/8) @ k^T + bias, masked -> -10000); out = attn @ v
// No-max softmax + 3-term bf16 hi/lo emulation (validated R3, rel_err ~1e-5).
// tcgen05 is NOT available (harness PTX target = compute_103 w/o 'a') -> mma.sync.

#define TEMPERATURE 8.0f
#define NEG_FILL -10000.0f

constexpr int B_ = 2, H_ = 12, S_ = 2048, D_ = 64;
constexpr int TQ = 128;           // q rows per block
constexpr int TK = 64;            // keys per tile
constexpr int LDT = 72;           // bf16 row stride (padded)
constexpr int SMEM_BF16 = 2 * TQ * LDT + 4 * TK * LDT;   // Qhi/Qlo + Khi/Klo/Vhi/Vlo
constexpr int SMEM_BYTES = SMEM_BF16 * 2;                // 73728 -> fits 3 blocks/SM

__device__ float g_inv[B_ * H_ * S_];   // per-row 1/sum scratch

// ---------- PTX helpers ----------
__device__ __forceinline__ uint32_t smem_u32(const void* p) {
    return (uint32_t)__cvta_generic_to_shared(p);
}
// pack two f32 -> bf16x2 reg, a in LOW half, b in HIGH half
__device__ __forceinline__ uint32_t pack_bf16(float a, float b) {
    uint32_t r;
    asm("cvt.rn.bf16x2.f32 %0, %1, %2;" : "=r"(r) : "f"(b), "f"(a));
    return r;
}
__device__ __forceinline__ void ldsm_x4(uint32_t addr, uint32_t& r0, uint32_t& r1,
                                        uint32_t& r2, uint32_t& r3) {
    asm volatile("ldmatrix.sync.aligned.m8n8.x4.shared.b16 {%0,%1,%2,%3}, [%4];"
                 : "=r"(r0), "=r"(r1), "=r"(r2), "=r"(r3) : "r"(addr));
}
__device__ __forceinline__ void ldsm_x2(uint32_t addr, uint32_t& r0, uint32_t& r1) {
    asm volatile("ldmatrix.sync.aligned.m8n8.x2.shared.b16 {%0,%1}, [%2];"
                 : "=r"(r0), "=r"(r1) : "r"(addr));
}
__device__ __forceinline__ void ldsm_x2t(uint32_t addr, uint32_t& r0, uint32_t& r1) {
    asm volatile("ldmatrix.sync.aligned.m8n8.x2.trans.shared.b16 {%0,%1}, [%2];"
                 : "=r"(r0), "=r"(r1) : "r"(addr));
}
__device__ __forceinline__ void mma_bf16(float& c0, float& c1, float& c2, float& c3,
                                         uint32_t a0, uint32_t a1, uint32_t a2, uint32_t a3,
                                         uint32_t b0, uint32_t b1) {
    asm volatile(
        "mma.sync.aligned.m16n8k16.row.col.f32.bf16.bf16.f32 "
        "{%0,%1,%2,%3}, {%4,%5,%6,%7}, {%8,%9}, {%0,%1,%2,%3};"
        : "+f"(c0), "+f"(c1), "+f"(c2), "+f"(c3)
        : "r"(a0), "r"(a1), "r"(a2), "r"(a3), "r"(b0), "r"(b1));
}
__device__ __forceinline__ void split2(float x, float& hi, float& lo) {
    hi = __bfloat162float(__float2bfloat16_rn(x));
    lo = x - hi;
}

// ================= Kernel 1: e = exp(logits), rowsums, out_unnorm = e@V =========
__global__ __launch_bounds__(256, 3) void attn_k1(
    const float* __restrict__ q, const float* __restrict__ k,
    const float* __restrict__ v, const int* __restrict__ mask,
    const float* __restrict__ bias, float* __restrict__ out,
    float* __restrict__ attn)
{
    extern __shared__ __nv_bfloat16 sm[];

    __nv_bfloat16* Qhi = sm;
    __nv_bfloat16* Qlo = Qhi + TQ * LDT;
    __nv_bfloat16* Khi = Qlo + TQ * LDT;
    __nv_bfloat16* Klo = Khi + TK * LDT;
    __nv_bfloat16* Vhi = Klo + TK * LDT;
    __nv_bfloat16* Vlo = Vhi + TK * LDT;

    const int t    = threadIdx.x;
    const int lane = t & 31;
    const int w    = t >> 5;            // 8 warps, warp owns q rows 16w..16w+15
    const int bh   = blockIdx.y;
    const int b    = bh / H_;
    const int h    = bh % H_;
    const int q0   = blockIdx.x * TQ;

    const float* qb    = q    + ((long)bh * S_ + q0) * D_;
    const float* kb    = k    + (long)bh * S_ * D_;
    const float* vb    = v    + (long)bh * S_ * D_;
    const int*   maskb = mask + (long)b * S_;
    float*       attb  = attn + ((long)bh * S_ + q0) * S_;
    const float* biasb = bias + ((long)h  * S_ + q0) * S_;

    // ---- load Q (split hi/lo) ----
    #pragma unroll
    for (int i = 0; i < 8; i++) {
        int idx4 = t + i * 256;          // 2048 float4
        int r  = idx4 >> 4;
        int d4 = (idx4 & 15) * 4;
        float4 qv = *(const float4*)(qb + (long)r * D_ + d4);
        float xh, xl, yh, yl, zh, zl, wh, wl;
        split2(qv.x * (1.0f / TEMPERATURE), xh, xl);
        split2(qv.y * (1.0f / TEMPERATURE), yh, yl);
        split2(qv.z * (1.0f / TEMPERATURE), zh, zl);
        split2(qv.w * (1.0f / TEMPERATURE), wh, wl);
        uint32_t* ph = (uint32_t*)(Qhi + r * LDT + d4);
        uint32_t* pl = (uint32_t*)(Qlo + r * LDT + d4);
        ph[0] = pack_bf16(xh, yh); ph[1] = pack_bf16(zh, wh);
        pl[0] = pack_bf16(xl, yl); pl[1] = pack_bf16(zl, wl);
    }

    const int mrow = w * 16;
    const int g    = lane >> 2;          // 0..7
    const int qr0  = mrow + g;
    const int qr1  = mrow + g + 8;

    // A-fragment base address (Q): row = mrow + lane%16, col = 8*(lane/16)
    const uint32_t qa_off = ((uint32_t)(mrow + (lane & 15)) * LDT + 8u * (lane >> 4)) * 2u;
    const uint32_t qhi_base = smem_u32(Qhi) + qa_off;
    const uint32_t qlo_base = smem_u32(Qlo) + qa_off;

    const int li  = lane & 15;
    // QK B-frag addr pattern: row = nt*8 + (li&7), col = ks*16 + 8*(li>>3)
    const uint32_t kb_off = ((uint32_t)(li & 7) * LDT + 8u * (li >> 3)) * 2u;
    // PV B-frag addr pattern: row = ks2*16 + li, col = dn*8
    const uint32_t vb_off = ((uint32_t)li * LDT) * 2u;

    float accO[8][4];
    #pragma unroll
    for (int i = 0; i < 8; i++)
        #pragma unroll
        for (int j = 0; j < 4; j++) accO[i][j] = 0.0f;
    float sum0 = 0.0f, sum1 = 0.0f;

    for (int kt = 0; kt < S_ / TK; kt++) {
        __syncthreads();
        const int k0 = kt * TK;
        // ---- load K, V tiles (split hi/lo) ----
        #pragma unroll
        for (int i = 0; i < 4; i++) {
            int idx4 = t + i * 256;      // 1024 float4
            int r  = idx4 >> 4;
            int d4 = (idx4 & 15) * 4;
            float4 kv = *(const float4*)(kb + (long)(k0 + r) * D_ + d4);
            float xh, xl, yh, yl, zh, zl, wh, wl;
            split2(kv.x, xh, xl); split2(kv.y, yh, yl);
            split2(kv.z, zh, zl); split2(kv.w, wh, wl);
            uint32_t* ph = (uint32_t*)(Khi + r * LDT + d4);
            uint32_t* pl = (uint32_t*)(Klo + r * LDT + d4);
            ph[0] = pack_bf16(xh, yh); ph[1] = pack_bf16(zh, wh);
            pl[0] = pack_bf16(xl, yl); pl[1] = pack_bf16(zl, wl);
            float4 vv = *(const float4*)(vb + (long)(k0 + r) * D_ + d4);
            split2(vv.x, xh, xl); split2(vv.y, yh, yl);
            split2(vv.z, zh, zl); split2(vv.w, wh, wl);
            ph = (uint32_t*)(Vhi + r * LDT + d4);
            pl = (uint32_t*)(Vlo + r * LDT + d4);
            ph[0] = pack_bf16(xh, yh); ph[1] = pack_bf16(zh, wh);
            pl[0] = pack_bf16(xl, yl); pl[1] = pack_bf16(zl, wl);
        }
        __syncthreads();

        // Two phases of 4 n-tiles each: halves live register pressure so we
        // fit the 85-reg budget for 3 blocks/SM (kills the wave tail).
        #pragma unroll
        for (int phase = 0; phase < 2; phase++) {
            // ---- QK^T for n-tiles phase*4 .. phase*4+3 ----
            float acc[4][4];
            #pragma unroll
            for (int i = 0; i < 4; i++)
                #pragma unroll
                for (int j = 0; j < 4; j++) acc[i][j] = 0.0f;

            #pragma unroll
            for (int ks = 0; ks < 4; ks++) {
                uint32_t ah0, ah1, ah2, ah3, al0, al1, al2, al3;
                ldsm_x4(qhi_base + ks * 32u, ah0, ah1, ah2, ah3);
                ldsm_x4(qlo_base + ks * 32u, al0, al1, al2, al3);
                const uint32_t krow = smem_u32(Khi) + kb_off + ks * 32u;
                const uint32_t krol = smem_u32(Klo) + kb_off + ks * 32u;
                #pragma unroll
                for (int ntl = 0; ntl < 4; ntl++) {
                    const int nt = phase * 4 + ntl;
                    uint32_t bh0, bh1, bl0, bl1;
                    ldsm_x2(krow + (uint32_t)(nt * 8 * LDT) * 2u, bh0, bh1);
                    ldsm_x2(krol + (uint32_t)(nt * 8 * LDT) * 2u, bl0, bl1);
                    mma_bf16(acc[ntl][0], acc[ntl][1], acc[ntl][2], acc[ntl][3],
                             ah0, ah1, ah2, ah3, bh0, bh1);
                    mma_bf16(acc[ntl][0], acc[ntl][1], acc[ntl][2], acc[ntl][3],
                             ah0, ah1, ah2, ah3, bl0, bl1);
                    mma_bf16(acc[ntl][0], acc[ntl][1], acc[ntl][2], acc[ntl][3],
                             al0, al1, al2, al3, bh0, bh1);
                }
            }

            // ---- epilogue + PV per 16-key group (2 n-tiles) ----
            #pragma unroll
            for (int ks2l = 0; ks2l < 2; ks2l++) {
                const int ks2 = phase * 2 + ks2l;
                uint32_t fh[2][2], fl[2][2];
                #pragma unroll
                for (int half = 0; half < 2; half++) {
                    const int nt  = ks2 * 2 + half;
                    const int ai  = nt - phase * 4;
                    const int gk  = k0 + nt * 8 + (lane & 3) * 2;
                    const int2  mv  = *(const int2*)(maskb + gk);
                    const float2 bv0 = *(const float2*)(biasb + (long)qr0 * S_ + gk);
                    const float2 bv1 = *(const float2*)(biasb + (long)qr1 * S_ + gk);
                    float l00 = acc[ai][0] + bv0.x; if (mv.x == 0) l00 = NEG_FILL;
                    float l01 = acc[ai][1] + bv0.y; if (mv.y == 0) l01 = NEG_FILL;
                    float l10 = acc[ai][2] + bv1.x; if (mv.x == 0) l10 = NEG_FILL;
                    float l11 = acc[ai][3] + bv1.y; if (mv.y == 0) l11 = NEG_FILL;
                    float e00 = __expf(l00), e01 = __expf(l01);
                    float e10 = __expf(l10), e11 = __expf(l11);
                    sum0 += e00 + e01;
                    sum1 += e10 + e11;
                    *(float2*)(attb + (long)qr0 * S_ + gk) = make_float2(e00, e01);
                    *(float2*)(attb + (long)qr1 * S_ + gk) = make_float2(e10, e11);
                    float h00, o00, h01, o01, h10, o10, h11, o11;
                    split2(e00, h00, o00); split2(e01, h01, o01);
                    split2(e10, h10, o10); split2(e11, h11, o11);
                    fh[half][0] = pack_bf16(h00, h01);   // row g
                    fh[half][1] = pack_bf16(h10, h11);   // row g+8
                    fl[half][0] = pack_bf16(o00, o01);
                    fl[half][1] = pack_bf16(o10, o11);
                }
                const uint32_t vrow = smem_u32(Vhi) + vb_off + (uint32_t)(ks2 * 16 * LDT) * 2u;
                const uint32_t vrol = smem_u32(Vlo) + vb_off + (uint32_t)(ks2 * 16 * LDT) * 2u;
                #pragma unroll
                for (int dn = 0; dn < 8; dn++) {
                    uint32_t bh0, bh1, bl0, bl1;
                    ldsm_x2t(vrow + dn * 16u, bh0, bh1);
                    ldsm_x2t(vrol + dn * 16u, bl0, bl1);
                    mma_bf16(accO[dn][0], accO[dn][1], accO[dn][2], accO[dn][3],
                             fh[0][0], fh[0][1], fh[1][0], fh[1][1], bh0, bh1);
                    mma_bf16(accO[dn][0], accO[dn][1], accO[dn][2], accO[dn][3],
                             fh[0][0], fh[0][1], fh[1][0], fh[1][1], bl0, bl1);
                    mma_bf16(accO[dn][0], accO[dn][1], accO[dn][2], accO[dn][3],
                             fl[0][0], fl[0][1], fl[1][0], fl[1][1], bh0, bh1);
                }
            }
        }
    }

    // ---- row sums: reduce over quad (lanes sharing a row) ----
    sum0 += __shfl_xor_sync(0xffffffffu, sum0, 1);
    sum0 += __shfl_xor_sync(0xffffffffu, sum0, 2);
    sum1 += __shfl_xor_sync(0xffffffffu, sum1, 1);
    sum1 += __shfl_xor_sync(0xffffffffu, sum1, 2);
    const float inv0 = 1.0f / sum0;
    const float inv1 = 1.0f / sum1;
    if ((lane & 3) == 0) {
        g_inv[(long)bh * S_ + q0 + qr0] = inv0;
        g_inv[(long)bh * S_ + q0 + qr1] = inv1;
    }

    // ---- write out (normalized) ----
    #pragma unroll
    for (int dn = 0; dn < 8; dn++) {
        const int dc = dn * 8 + (lane & 3) * 2;
        *(float2*)(out + ((long)bh * S_ + q0 + qr0) * D_ + dc) =
            make_float2(accO[dn][0] * inv0, accO[dn][1] * inv0);
        *(float2*)(out + ((long)bh * S_ + q0 + qr1) * D_ + dc) =
            make_float2(accO[dn][2] * inv1, accO[dn][3] * inv1);
    }
}

// ================= Kernel 2: attn row normalize (at DRAM roofline) =================
__global__ __launch_bounds__(128) void attn_norm(float* __restrict__ attn) {
    const long row = blockIdx.x;
    const float inv = g_inv[row];
    float4* p = (float4*)(attn + row * S_);
    #pragma unroll
    for (int i = threadIdx.x; i < S_ / 4; i += 128) {
        float4 x = p[i];
        x.x *= inv; x.y *= inv; x.z *= inv; x.w *= inv;
        p[i] = x;
    }
}

extern "C" void kernel_launch(void* const* d_in, const int* in_sizes, int n_in,
                              void* d_out, int out_size) {
    const float* q    = (const float*)d_in[0];
    const float* k    = (const float*)d_in[1];
    const float* v    = (const float*)d_in[2];
    const int*   mask = (const int*)  d_in[3];
    const float* bias = (const float*)d_in[4];

    float* out  = (float*)d_out;
    float* attn = (float*)d_out + (long)B_ * H_ * S_ * D_;

    static int configured = 0;
    if (!configured) {
        cudaFuncSetAttribute(attn_k1,
                             cudaFuncAttributeMaxDynamicSharedMemorySize, SMEM_BYTES);
        configured = 1;
    }

    dim3 grid1(S_ / TQ, B_ * H_);        // (16, 24)
    attn_k1<<<grid1, 256, SMEM_BYTES>>>(q, k, v, mask, bias, out, attn);
    attn_norm<<<B_ * H_ * S_, 128>>>(attn);
}

// round 6
// speedup vs baseline: 1.2661x; 1.2661x over previous
#include <cuda_runtime.h>
#include <cuda_bf16.h>
#include <cstdint>

// q,k,v: [2,12,2048,64] f32; mask: [2,1,1,2048] i32; bias: [1,12,2048,2048] f32
// out region: out [2,12,2048,64] then attn [2,12,2048,2048]
// attn = softmax((q/8) @ k^T + bias, masked -> -10000); out = attn @ v
// No-max softmax + 3-term bf16 hi/lo emulation (validated R3, rel_err ~1e-5).
// tcgen05 unavailable (harness targets compute_103 w/o 'a') -> mma.sync path.

#define TEMPERATURE 8.0f
#define NEG_FILL -10000.0f

constexpr int B_ = 2, H_ = 12, S_ = 2048, D_ = 64;
constexpr int TQ = 128;           // q rows per block
constexpr int TK = 64;            // keys per tile
constexpr int LDT = 72;           // bf16 row stride (padded)
// bf16 region: Qhi/Qlo (128x72 each) + Khi/Klo/Vhi/Vlo (64x72 each) = 73728 B
constexpr int BF16_BYTES = (2 * TQ * LDT + 4 * TK * LDT) * 2;
// raw f32 staging for next tile's K and V (64x64 each) = 32768 B
constexpr int RAW_BYTES  = 2 * TK * D_ * 4;
constexpr int SMEM_BYTES = BF16_BYTES + RAW_BYTES;       // 106496 -> 2 blocks/SM

__device__ float g_inv[B_ * H_ * S_];   // per-row 1/sum scratch

// ---------- PTX helpers ----------
__device__ __forceinline__ uint32_t smem_u32(const void* p) {
    return (uint32_t)__cvta_generic_to_shared(p);
}
__device__ __forceinline__ uint32_t pack_bf16(float a, float b) {   // a -> low half
    uint32_t r;
    asm("cvt.rn.bf16x2.f32 %0, %1, %2;" : "=r"(r) : "f"(b), "f"(a));
    return r;
}
__device__ __forceinline__ void ldsm_x4(uint32_t addr, uint32_t& r0, uint32_t& r1,
                                        uint32_t& r2, uint32_t& r3) {
    asm volatile("ldmatrix.sync.aligned.m8n8.x4.shared.b16 {%0,%1,%2,%3}, [%4];"
                 : "=r"(r0), "=r"(r1), "=r"(r2), "=r"(r3) : "r"(addr));
}
__device__ __forceinline__ void ldsm_x4t(uint32_t addr, uint32_t& r0, uint32_t& r1,
                                         uint32_t& r2, uint32_t& r3) {
    asm volatile("ldmatrix.sync.aligned.m8n8.x4.trans.shared.b16 {%0,%1,%2,%3}, [%4];"
                 : "=r"(r0), "=r"(r1), "=r"(r2), "=r"(r3) : "r"(addr));
}
__device__ __forceinline__ void mma_bf16(float& c0, float& c1, float& c2, float& c3,
                                         uint32_t a0, uint32_t a1, uint32_t a2, uint32_t a3,
                                         uint32_t b0, uint32_t b1) {
    asm volatile(
        "mma.sync.aligned.m16n8k16.row.col.f32.bf16.bf16.f32 "
        "{%0,%1,%2,%3}, {%4,%5,%6,%7}, {%8,%9}, {%0,%1,%2,%3};"
        : "+f"(c0), "+f"(c1), "+f"(c2), "+f"(c3)
        : "r"(a0), "r"(a1), "r"(a2), "r"(a3), "r"(b0), "r"(b1));
}
__device__ __forceinline__ void split2(float x, float& hi, float& lo) {
    hi = __bfloat162float(__float2bfloat16_rn(x));
    lo = x - hi;
}
__device__ __forceinline__ void cp_async16(uint32_t saddr, const void* gaddr) {
    asm volatile("cp.async.cg.shared.global [%0], [%1], 16;"
                 :: "r"(saddr), "l"(gaddr));
}
__device__ __forceinline__ void cp_commit() {
    asm volatile("cp.async.commit_group;" ::: "memory");
}
__device__ __forceinline__ void cp_wait_all() {
    asm volatile("cp.async.wait_group 0;" ::: "memory");
}

// ================= Kernel 1: e = exp(logits), rowsums, out_unnorm = e@V =========
__global__ __launch_bounds__(256, 2) void attn_k1(
    const float* __restrict__ q, const float* __restrict__ k,
    const float* __restrict__ v, const int* __restrict__ mask,
    const float* __restrict__ bias, float* __restrict__ out,
    float* __restrict__ attn)
{
    extern __shared__ char smraw[];
    __nv_bfloat16* sm = (__nv_bfloat16*)smraw;

    __nv_bfloat16* Qhi = sm;
    __nv_bfloat16* Qlo = Qhi + TQ * LDT;
    __nv_bfloat16* Khi = Qlo + TQ * LDT;
    __nv_bfloat16* Klo = Khi + TK * LDT;
    __nv_bfloat16* Vhi = Klo + TK * LDT;
    __nv_bfloat16* Vlo = Vhi + TK * LDT;
    float* rawK = (float*)(smraw + BF16_BYTES);          // [64*64] f32
    float* rawV = rawK + TK * D_;                        // [64*64] f32

    const int t    = threadIdx.x;
    const int lane = t & 31;
    const int w    = t >> 5;            // 8 warps, warp owns q rows 16w..16w+15
    const int bh   = blockIdx.y;
    const int b    = bh & 1;            // b innermost -> adjacent blocks share bias (L2)
    const int h    = bh >> 1;
    const int q0   = blockIdx.x * TQ;
    const int bhq  = b * H_ + h;        // qkv/out/attn head index

    const float* qb    = q    + ((long)bhq * S_ + q0) * D_;
    const float* kb    = k    + (long)bhq * S_ * D_;
    const float* vb    = v    + (long)bhq * S_ * D_;
    const int*   maskb = mask + (long)b * S_;
    float*       attb  = attn + ((long)bhq * S_ + q0) * S_;
    const float* biasb = bias + ((long)h  * S_ + q0) * S_;

    // ---- prologue: stage tile 0 K/V raw via cp.async ----
    const uint32_t rawK_a = smem_u32(rawK);
    const uint32_t rawV_a = smem_u32(rawV);
    #pragma unroll
    for (int i = 0; i < 4; i++) {
        int idx4 = t + i * 256;          // 1024 float4 = contiguous 64x64 tile
        cp_async16(rawK_a + idx4 * 16u, kb + idx4 * 4);
        cp_async16(rawV_a + idx4 * 16u, vb + idx4 * 4);
    }
    cp_commit();

    // ---- load Q (split hi/lo) directly from gmem ----
    #pragma unroll
    for (int i = 0; i < 8; i++) {
        int idx4 = t + i * 256;          // 2048 float4
        int r  = idx4 >> 4;
        int d4 = (idx4 & 15) * 4;
        float4 qv = *(const float4*)(qb + (long)r * D_ + d4);
        float xh, xl, yh, yl, zh, zl, wh, wl;
        split2(qv.x * (1.0f / TEMPERATURE), xh, xl);
        split2(qv.y * (1.0f / TEMPERATURE), yh, yl);
        split2(qv.z * (1.0f / TEMPERATURE), zh, zl);
        split2(qv.w * (1.0f / TEMPERATURE), wh, wl);
        uint32_t* ph = (uint32_t*)(Qhi + r * LDT + d4);
        uint32_t* pl = (uint32_t*)(Qlo + r * LDT + d4);
        ph[0] = pack_bf16(xh, yh); ph[1] = pack_bf16(zh, wh);
        pl[0] = pack_bf16(xl, yl); pl[1] = pack_bf16(zl, wl);
    }

    const int mrow = w * 16;
    const int g    = lane >> 2;          // 0..7
    const int qr0  = mrow + g;
    const int qr1  = mrow + g + 8;

    // Q A-frag base: row = mrow + lane%16, col = 8*(lane/16)
    const uint32_t qa_off = ((uint32_t)(mrow + (lane & 15)) * LDT + 8u * (lane >> 4)) * 2u;
    const uint32_t qhi_base = smem_u32(Qhi) + qa_off;
    const uint32_t qlo_base = smem_u32(Qlo) + qa_off;

    // K x4 B-frag (2 n-tiles per load): grp=lane>>3
    //   row_in = (grp>>1)*8 + (lane&7), col_off = (grp&1)*8
    const int kgrp = lane >> 3;
    const uint32_t kx4_off =
        ((uint32_t)((kgrp >> 1) * 8 + (lane & 7)) * LDT + (uint32_t)(kgrp & 1) * 8u) * 2u;
    const uint32_t khi_b = smem_u32(Khi) + kx4_off;
    const uint32_t klo_b = smem_u32(Klo) + kx4_off;

    // V x4t B-frag (2 d-tiles per load): row = ks2*16 + (lane&15), col = (dnp + lane>>4)*8
    const uint32_t vx4_off =
        ((uint32_t)(lane & 15) * LDT + (uint32_t)(lane >> 4) * 8u) * 2u;
    const uint32_t vhi_b = smem_u32(Vhi) + vx4_off;
    const uint32_t vlo_b = smem_u32(Vlo) + vx4_off;

    float accO[8][4];
    #pragma unroll
    for (int i = 0; i < 8; i++)
        #pragma unroll
        for (int j = 0; j < 4; j++) accO[i][j] = 0.0f;
    float sum0 = 0.0f, sum1 = 0.0f;

    for (int kt = 0; kt < S_ / TK; kt++) {
        const int k0 = kt * TK;
        cp_wait_all();
        __syncthreads();   // raw tile ready; bf16 K/V free from previous tile

        // ---- convert raw (smem) -> bf16 hi/lo smem ----
        #pragma unroll
        for (int i = 0; i < 4; i++) {
            int idx4 = t + i * 256;      // same partition as the cp.async that staged it
            int r  = idx4 >> 4;
            int d4 = (idx4 & 15) * 4;
            float4 kv = *(const float4*)(rawK + idx4 * 4);
            float xh, xl, yh, yl, zh, zl, wh, wl;
            split2(kv.x, xh, xl); split2(kv.y, yh, yl);
            split2(kv.z, zh, zl); split2(kv.w, wh, wl);
            uint32_t* ph = (uint32_t*)(Khi + r * LDT + d4);
            uint32_t* pl = (uint32_t*)(Klo + r * LDT + d4);
            ph[0] = pack_bf16(xh, yh); ph[1] = pack_bf16(zh, wh);
            pl[0] = pack_bf16(xl, yl); pl[1] = pack_bf16(zl, wl);
            float4 vv = *(const float4*)(rawV + idx4 * 4);
            split2(vv.x, xh, xl); split2(vv.y, yh, yl);
            split2(vv.z, zh, zl); split2(vv.w, wh, wl);
            ph = (uint32_t*)(Vhi + r * LDT + d4);
            pl = (uint32_t*)(Vlo + r * LDT + d4);
            ph[0] = pack_bf16(xh, yh); ph[1] = pack_bf16(zh, wh);
            pl[0] = pack_bf16(xl, yl); pl[1] = pack_bf16(zl, wl);
        }
        __syncthreads();   // converts done everywhere before raw is overwritten

        // ---- stage next tile's raw K/V (overlaps with MMAs below) ----
        if (kt + 1 < S_ / TK) {
            const float* knext = kb + (long)(k0 + TK) * D_;
            const float* vnext = vb + (long)(k0 + TK) * D_;
            #pragma unroll
            for (int i = 0; i < 4; i++) {
                int idx4 = t + i * 256;
                cp_async16(rawK_a + idx4 * 16u, knext + idx4 * 4);
                cp_async16(rawV_a + idx4 * 16u, vnext + idx4 * 4);
            }
            cp_commit();
        }

        // ---- QK^T: logits tile 16(q) x 64(k) per warp ----
        float acc[8][4];
        #pragma unroll
        for (int i = 0; i < 8; i++)
            #pragma unroll
            for (int j = 0; j < 4; j++) acc[i][j] = 0.0f;

        #pragma unroll
        for (int ks = 0; ks < 4; ks++) {
            uint32_t ah0, ah1, ah2, ah3, al0, al1, al2, al3;
            ldsm_x4(qhi_base + ks * 32u, ah0, ah1, ah2, ah3);
            ldsm_x4(qlo_base + ks * 32u, al0, al1, al2, al3);
            #pragma unroll
            for (int ntp = 0; ntp < 8; ntp += 2) {
                const uint32_t off = (uint32_t)(ntp * 8 * LDT) * 2u + ks * 32u;
                uint32_t bh0, bh1, bh2, bh3, bl0, bl1, bl2, bl3;
                ldsm_x4(khi_b + off, bh0, bh1, bh2, bh3);
                ldsm_x4(klo_b + off, bl0, bl1, bl2, bl3);
                mma_bf16(acc[ntp][0], acc[ntp][1], acc[ntp][2], acc[ntp][3],
                         ah0, ah1, ah2, ah3, bh0, bh1);
                mma_bf16(acc[ntp][0], acc[ntp][1], acc[ntp][2], acc[ntp][3],
                         ah0, ah1, ah2, ah3, bl0, bl1);
                mma_bf16(acc[ntp][0], acc[ntp][1], acc[ntp][2], acc[ntp][3],
                         al0, al1, al2, al3, bh0, bh1);
                mma_bf16(acc[ntp + 1][0], acc[ntp + 1][1], acc[ntp + 1][2], acc[ntp + 1][3],
                         ah0, ah1, ah2, ah3, bh2, bh3);
                mma_bf16(acc[ntp + 1][0], acc[ntp + 1][1], acc[ntp + 1][2], acc[ntp + 1][3],
                         ah0, ah1, ah2, ah3, bl2, bl3);
                mma_bf16(acc[ntp + 1][0], acc[ntp + 1][1], acc[ntp + 1][2], acc[ntp + 1][3],
                         al0, al1, al2, al3, bh2, bh3);
            }
        }

        // ---- epilogue: bias, mask, exp, write e, build PV A-frags ----
        uint32_t ehi[8][2], elo[8][2];
        #pragma unroll
        for (int nt = 0; nt < 8; nt++) {
            const int gk = k0 + nt * 8 + (lane & 3) * 2;
            const int2 mv = *(const int2*)(maskb + gk);
            float2 bv0 = *(const float2*)(biasb + (long)qr0 * S_ + gk);
            float2 bv1 = *(const float2*)(biasb + (long)qr1 * S_ + gk);
            float l00 = acc[nt][0] + bv0.x; if (mv.x == 0) l00 = NEG_FILL;
            float l01 = acc[nt][1] + bv0.y; if (mv.y == 0) l01 = NEG_FILL;
            float l10 = acc[nt][2] + bv1.x; if (mv.x == 0) l10 = NEG_FILL;
            float l11 = acc[nt][3] + bv1.y; if (mv.y == 0) l11 = NEG_FILL;
            float e00 = __expf(l00), e01 = __expf(l01);
            float e10 = __expf(l10), e11 = __expf(l11);
            sum0 += e00 + e01;
            sum1 += e10 + e11;
            *(float2*)(attb + (long)qr0 * S_ + gk) = make_float2(e00, e01);
            *(float2*)(attb + (long)qr1 * S_ + gk) = make_float2(e10, e11);
            float h00, o00, h01, o01, h10, o10, h11, o11;
            split2(e00, h00, o00); split2(e01, h01, o01);
            split2(e10, h10, o10); split2(e11, h11, o11);
            ehi[nt][0] = pack_bf16(h00, h01);  // row g,  k even/odd
            ehi[nt][1] = pack_bf16(h10, h11);  // row g+8
            elo[nt][0] = pack_bf16(o00, o01);
            elo[nt][1] = pack_bf16(o10, o11);
        }

        // ---- PV: out[16 x 64] += E[16 x 64] @ V[64 x 64] ----
        #pragma unroll
        for (int ks2 = 0; ks2 < 4; ks2++) {
            uint32_t a0h = ehi[2 * ks2][0],     a1h = ehi[2 * ks2][1];
            uint32_t a2h = ehi[2 * ks2 + 1][0], a3h = ehi[2 * ks2 + 1][1];
            uint32_t a0l = elo[2 * ks2][0],     a1l = elo[2 * ks2][1];
            uint32_t a2l = elo[2 * ks2 + 1][0], a3l = elo[2 * ks2 + 1][1];
            const uint32_t roff = (uint32_t)(ks2 * 16 * LDT) * 2u;
            #pragma unroll
            for (int dnp = 0; dnp < 8; dnp += 2) {
                uint32_t bh0, bh1, bh2, bh3, bl0, bl1, bl2, bl3;
                ldsm_x4t(vhi_b + roff + dnp * 16u, bh0, bh1, bh2, bh3);
                ldsm_x4t(vlo_b + roff + dnp * 16u, bl0, bl1, bl2, bl3);
                mma_bf16(accO[dnp][0], accO[dnp][1], accO[dnp][2], accO[dnp][3],
                         a0h, a1h, a2h, a3h, bh0, bh1);
                mma_bf16(accO[dnp][0], accO[dnp][1], accO[dnp][2], accO[dnp][3],
                         a0h, a1h, a2h, a3h, bl0, bl1);
                mma_bf16(accO[dnp][0], accO[dnp][1], accO[dnp][2], accO[dnp][3],
                         a0l, a1l, a2l, a3l, bh0, bh1);
                mma_bf16(accO[dnp + 1][0], accO[dnp + 1][1], accO[dnp + 1][2], accO[dnp + 1][3],
                         a0h, a1h, a2h, a3h, bh2, bh3);
                mma_bf16(accO[dnp + 1][0], accO[dnp + 1][1], accO[dnp + 1][2], accO[dnp + 1][3],
                         a0h, a1h, a2h, a3h, bl2, bl3);
                mma_bf16(accO[dnp + 1][0], accO[dnp + 1][1], accO[dnp + 1][2], accO[dnp + 1][3],
                         a0l, a1l, a2l, a3l, bh2, bh3);
            }
        }
    }

    // ---- row sums: reduce over quad (lanes sharing a row) ----
    sum0 += __shfl_xor_sync(0xffffffffu, sum0, 1);
    sum0 += __shfl_xor_sync(0xffffffffu, sum0, 2);
    sum1 += __shfl_xor_sync(0xffffffffu, sum1, 1);
    sum1 += __shfl_xor_sync(0xffffffffu, sum1, 2);
    const float inv0 = 1.0f / sum0;
    const float inv1 = 1.0f / sum1;
    if ((lane & 3) == 0) {
        g_inv[(long)bhq * S_ + q0 + qr0] = inv0;
        g_inv[(long)bhq * S_ + q0 + qr1] = inv1;
    }

    // ---- write out (normalized) ----
    #pragma unroll
    for (int dn = 0; dn < 8; dn++) {
        const int dc = dn * 8 + (lane & 3) * 2;
        *(float2*)(out + ((long)bhq * S_ + q0 + qr0) * D_ + dc) =
            make_float2(accO[dn][0] * inv0, accO[dn][1] * inv0);
        *(float2*)(out + ((long)bhq * S_ + q0 + qr1) * D_ + dc) =
            make_float2(accO[dn][2] * inv1, accO[dn][3] * inv1);
    }
}

// ================= Kernel 2: attn row normalize (at DRAM roofline) =================
__global__ __launch_bounds__(128) void attn_norm(float* __restrict__ attn) {
    const long row = blockIdx.x;
    const float inv = g_inv[row];
    float4* p = (float4*)(attn + row * S_);
    #pragma unroll
    for (int i = threadIdx.x; i < S_ / 4; i += 128) {
        float4 x = p[i];
        x.x *= inv; x.y *= inv; x.z *= inv; x.w *= inv;
        p[i] = x;
    }
}

extern "C" void kernel_launch(void* const* d_in, const int* in_sizes, int n_in,
                              void* d_out, int out_size) {
    const float* q    = (const float*)d_in[0];
    const float* k    = (const float*)d_in[1];
    const float* v    = (const float*)d_in[2];
    const int*   mask = (const int*)  d_in[3];
    const float* bias = (const float*)d_in[4];

    float* out  = (float*)d_out;
    float* attn = (float*)d_out + (long)B_ * H_ * S_ * D_;

    static int configured = 0;
    if (!configured) {
        cudaFuncSetAttribute(attn_k1,
                             cudaFuncAttributeMaxDynamicSharedMemorySize, SMEM_BYTES);
        configured = 1;
    }

    dim3 grid1(S_ / TQ, B_ * H_);        // (16, 24)
    attn_k1<<<grid1, 256, SMEM_BYTES>>>(q, k, v, mask, bias, out, attn);
    attn_norm<<<B_ * H_ * S_, 128>>>(attn);
}

// round 7
// speedup vs baseline: 1.4689x; 1.1602x over previous
#include <cuda_runtime.h>
#include <cuda_bf16.h>
#include <cstdint>

// q,k,v: [2,12,2048,64] f32; mask: [2,1,1,2048] i32; bias: [1,12,2048,2048] f32
// out region: out [2,12,2048,64] then attn [2,12,2048,2048]
// attn = softmax((q/8) @ k^T + bias, masked -> -10000); out = attn @ v
// No-max softmax (validated). QK = 3-term bf16 hi/lo emulation (attn accuracy).
// PV = 1-term fp16 with e pre-scaled by 2^-5 (out tolerance ~3e-4 << 1e-3).
// Normalization fused into k1 (block owns its attn rows exclusively).
// tcgen05 unavailable (harness targets compute_103 w/o 'a') -> mma.sync path.

#define TEMPERATURE 8.0f
#define NEG_FILL -10000.0f
#define ESCALE 0.03125f          // 2^-5, keeps fp16(e) far from overflow
#define ESCALE_INV 32.0f

constexpr int B_ = 2, H_ = 12, S_ = 2048, D_ = 64;
constexpr int TQ = 128;           // q rows per block
constexpr int TK = 64;            // keys per tile
constexpr int LDT = 72;           // 16-bit row stride (padded)
// 16-bit region: Qhi/Qlo (128x72) + Khi/Klo (64x72) + Vh (64x72)
constexpr int BF16_BYTES = (2 * TQ * LDT + 3 * TK * LDT) * 2;   // 64512
// raw f32 staging for next tile's K and V (64x64 each)
constexpr int RAW_BYTES  = 2 * TK * D_ * 4;                     // 32768
constexpr int SMEM_BYTES = BF16_BYTES + RAW_BYTES;              // 97280 -> 2 blocks/SM

// ---------- PTX helpers ----------
__device__ __forceinline__ uint32_t smem_u32(const void* p) {
    return (uint32_t)__cvta_generic_to_shared(p);
}
__device__ __forceinline__ uint32_t pack_bf16(float a, float b) {   // a -> low half
    uint32_t r;
    asm("cvt.rn.bf16x2.f32 %0, %1, %2;" : "=r"(r) : "f"(b), "f"(a));
    return r;
}
__device__ __forceinline__ uint32_t pack_f16(float a, float b) {    // a -> low half
    uint32_t r;
    asm("cvt.rn.f16x2.f32 %0, %1, %2;" : "=r"(r) : "f"(b), "f"(a));
    return r;
}
__device__ __forceinline__ void ldsm_x4(uint32_t addr, uint32_t& r0, uint32_t& r1,
                                        uint32_t& r2, uint32_t& r3) {
    asm volatile("ldmatrix.sync.aligned.m8n8.x4.shared.b16 {%0,%1,%2,%3}, [%4];"
                 : "=r"(r0), "=r"(r1), "=r"(r2), "=r"(r3) : "r"(addr));
}
__device__ __forceinline__ void ldsm_x4t(uint32_t addr, uint32_t& r0, uint32_t& r1,
                                         uint32_t& r2, uint32_t& r3) {
    asm volatile("ldmatrix.sync.aligned.m8n8.x4.trans.shared.b16 {%0,%1,%2,%3}, [%4];"
                 : "=r"(r0), "=r"(r1), "=r"(r2), "=r"(r3) : "r"(addr));
}
__device__ __forceinline__ void mma_bf16(float& c0, float& c1, float& c2, float& c3,
                                         uint32_t a0, uint32_t a1, uint32_t a2, uint32_t a3,
                                         uint32_t b0, uint32_t b1) {
    asm volatile(
        "mma.sync.aligned.m16n8k16.row.col.f32.bf16.bf16.f32 "
        "{%0,%1,%2,%3}, {%4,%5,%6,%7}, {%8,%9}, {%0,%1,%2,%3};"
        : "+f"(c0), "+f"(c1), "+f"(c2), "+f"(c3)
        : "r"(a0), "r"(a1), "r"(a2), "r"(a3), "r"(b0), "r"(b1));
}
__device__ __forceinline__ void mma_f16(float& c0, float& c1, float& c2, float& c3,
                                        uint32_t a0, uint32_t a1, uint32_t a2, uint32_t a3,
                                        uint32_t b0, uint32_t b1) {
    asm volatile(
        "mma.sync.aligned.m16n8k16.row.col.f32.f16.f16.f32 "
        "{%0,%1,%2,%3}, {%4,%5,%6,%7}, {%8,%9}, {%0,%1,%2,%3};"
        : "+f"(c0), "+f"(c1), "+f"(c2), "+f"(c3)
        : "r"(a0), "r"(a1), "r"(a2), "r"(a3), "r"(b0), "r"(b1));
}
__device__ __forceinline__ void split2(float x, float& hi, float& lo) {
    hi = __bfloat162float(__float2bfloat16_rn(x));
    lo = x - hi;
}
__device__ __forceinline__ void cp_async16(uint32_t saddr, const void* gaddr) {
    asm volatile("cp.async.cg.shared.global [%0], [%1], 16;"
                 :: "r"(saddr), "l"(gaddr));
}
__device__ __forceinline__ void cp_commit() {
    asm volatile("cp.async.commit_group;" ::: "memory");
}
__device__ __forceinline__ void cp_wait_all() {
    asm volatile("cp.async.wait_group 0;" ::: "memory");
}

// ============== Fused kernel: e=exp(logits), rowsums, out, attn normalize =======
__global__ __launch_bounds__(256, 2) void attn_k1(
    const float* __restrict__ q, const float* __restrict__ k,
    const float* __restrict__ v, const int* __restrict__ mask,
    const float* __restrict__ bias, float* __restrict__ out,
    float* __restrict__ attn)
{
    extern __shared__ char smraw[];
    __shared__ float row_inv[TQ];
    __nv_bfloat16* sm = (__nv_bfloat16*)smraw;

    __nv_bfloat16* Qhi = sm;
    __nv_bfloat16* Qlo = Qhi + TQ * LDT;
    __nv_bfloat16* Khi = Qlo + TQ * LDT;
    __nv_bfloat16* Klo = Khi + TK * LDT;
    __nv_bfloat16* Vh  = Klo + TK * LDT;                 // fp16 storage (bit-agnostic)
    float* rawK = (float*)(smraw + BF16_BYTES);          // [64*64] f32
    float* rawV = rawK + TK * D_;                        // [64*64] f32

    const int t    = threadIdx.x;
    const int lane = t & 31;
    const int w    = t >> 5;            // 8 warps, warp owns q rows 16w..16w+15
    const int bh   = blockIdx.y;
    const int b    = bh & 1;            // b innermost -> adjacent blocks share bias (L2)
    const int h    = bh >> 1;
    const int q0   = blockIdx.x * TQ;
    const int bhq  = b * H_ + h;        // qkv/out/attn head index

    const float* qb    = q    + ((long)bhq * S_ + q0) * D_;
    const float* kb    = k    + (long)bhq * S_ * D_;
    const float* vb    = v    + (long)bhq * S_ * D_;
    const int*   maskb = mask + (long)b * S_;
    float*       attb  = attn + ((long)bhq * S_ + q0) * S_;
    const float* biasb = bias + ((long)h  * S_ + q0) * S_;

    // ---- prologue: stage tile 0 K/V raw via cp.async ----
    const uint32_t rawK_a = smem_u32(rawK);
    const uint32_t rawV_a = smem_u32(rawV);
    #pragma unroll
    for (int i = 0; i < 4; i++) {
        int idx4 = t + i * 256;          // 1024 float4 = contiguous 64x64 tile
        cp_async16(rawK_a + idx4 * 16u, kb + idx4 * 4);
        cp_async16(rawV_a + idx4 * 16u, vb + idx4 * 4);
    }
    cp_commit();

    // ---- load Q (split hi/lo) directly from gmem ----
    #pragma unroll
    for (int i = 0; i < 8; i++) {
        int idx4 = t + i * 256;          // 2048 float4
        int r  = idx4 >> 4;
        int d4 = (idx4 & 15) * 4;
        float4 qv = *(const float4*)(qb + (long)r * D_ + d4);
        float xh, xl, yh, yl, zh, zl, wh, wl;
        split2(qv.x * (1.0f / TEMPERATURE), xh, xl);
        split2(qv.y * (1.0f / TEMPERATURE), yh, yl);
        split2(qv.z * (1.0f / TEMPERATURE), zh, zl);
        split2(qv.w * (1.0f / TEMPERATURE), wh, wl);
        uint32_t* ph = (uint32_t*)(Qhi + r * LDT + d4);
        uint32_t* pl = (uint32_t*)(Qlo + r * LDT + d4);
        ph[0] = pack_bf16(xh, yh); ph[1] = pack_bf16(zh, wh);
        pl[0] = pack_bf16(xl, yl); pl[1] = pack_bf16(zl, wl);
    }

    const int mrow = w * 16;
    const int g    = lane >> 2;          // 0..7
    const int qr0  = mrow + g;
    const int qr1  = mrow + g + 8;

    // Q A-frag base: row = mrow + lane%16, col = 8*(lane/16)
    const uint32_t qa_off = ((uint32_t)(mrow + (lane & 15)) * LDT + 8u * (lane >> 4)) * 2u;
    const uint32_t qhi_base = smem_u32(Qhi) + qa_off;
    const uint32_t qlo_base = smem_u32(Qlo) + qa_off;

    // K x4 B-frag (2 n-tiles per load)
    const int kgrp = lane >> 3;
    const uint32_t kx4_off =
        ((uint32_t)((kgrp >> 1) * 8 + (lane & 7)) * LDT + (uint32_t)(kgrp & 1) * 8u) * 2u;
    const uint32_t khi_b = smem_u32(Khi) + kx4_off;
    const uint32_t klo_b = smem_u32(Klo) + kx4_off;

    // V x4t B-frag (2 d-tiles per load)
    const uint32_t vx4_off =
        ((uint32_t)(lane & 15) * LDT + (uint32_t)(lane >> 4) * 8u) * 2u;
    const uint32_t vh_b = smem_u32(Vh) + vx4_off;

    float accO[8][4];
    #pragma unroll
    for (int i = 0; i < 8; i++)
        #pragma unroll
        for (int j = 0; j < 4; j++) accO[i][j] = 0.0f;
    float sum0 = 0.0f, sum1 = 0.0f;

    for (int kt = 0; kt < S_ / TK; kt++) {
        const int k0 = kt * TK;
        cp_wait_all();
        __syncthreads();   // raw tile ready; 16-bit K/V buffers free from prev tile

        // ---- convert raw (smem) -> K bf16 hi/lo, V fp16 ----
        #pragma unroll
        for (int i = 0; i < 4; i++) {
            int idx4 = t + i * 256;
            int r  = idx4 >> 4;
            int d4 = (idx4 & 15) * 4;
            float4 kv = *(const float4*)(rawK + idx4 * 4);
            float xh, xl, yh, yl, zh, zl, wh, wl;
            split2(kv.x, xh, xl); split2(kv.y, yh, yl);
            split2(kv.z, zh, zl); split2(kv.w, wh, wl);
            uint32_t* ph = (uint32_t*)(Khi + r * LDT + d4);
            uint32_t* pl = (uint32_t*)(Klo + r * LDT + d4);
            ph[0] = pack_bf16(xh, yh); ph[1] = pack_bf16(zh, wh);
            pl[0] = pack_bf16(xl, yl); pl[1] = pack_bf16(zl, wl);
            float4 vv = *(const float4*)(rawV + idx4 * 4);
            uint32_t* pv = (uint32_t*)(Vh + r * LDT + d4);
            pv[0] = pack_f16(vv.x, vv.y); pv[1] = pack_f16(vv.z, vv.w);
        }
        __syncthreads();   // converts visible everywhere before raw is overwritten

        // ---- stage next tile's raw K/V (overlaps with MMAs below) ----
        if (kt + 1 < S_ / TK) {
            const float* knext = kb + (long)(k0 + TK) * D_;
            const float* vnext = vb + (long)(k0 + TK) * D_;
            #pragma unroll
            for (int i = 0; i < 4; i++) {
                int idx4 = t + i * 256;
                cp_async16(rawK_a + idx4 * 16u, knext + idx4 * 4);
                cp_async16(rawV_a + idx4 * 16u, vnext + idx4 * 4);
            }
            cp_commit();
        }

        // ---- QK^T: logits tile 16(q) x 64(k) per warp, 3-term bf16 ----
        float acc[8][4];
        #pragma unroll
        for (int i = 0; i < 8; i++)
            #pragma unroll
            for (int j = 0; j < 4; j++) acc[i][j] = 0.0f;

        #pragma unroll
        for (int ks = 0; ks < 4; ks++) {
            uint32_t ah0, ah1, ah2, ah3, al0, al1, al2, al3;
            ldsm_x4(qhi_base + ks * 32u, ah0, ah1, ah2, ah3);
            ldsm_x4(qlo_base + ks * 32u, al0, al1, al2, al3);
            #pragma unroll
            for (int ntp = 0; ntp < 8; ntp += 2) {
                const uint32_t off = (uint32_t)(ntp * 8 * LDT) * 2u + ks * 32u;
                uint32_t bh0, bh1, bh2, bh3, bl0, bl1, bl2, bl3;
                ldsm_x4(khi_b + off, bh0, bh1, bh2, bh3);
                ldsm_x4(klo_b + off, bl0, bl1, bl2, bl3);
                mma_bf16(acc[ntp][0], acc[ntp][1], acc[ntp][2], acc[ntp][3],
                         ah0, ah1, ah2, ah3, bh0, bh1);
                mma_bf16(acc[ntp][0], acc[ntp][1], acc[ntp][2], acc[ntp][3],
                         ah0, ah1, ah2, ah3, bl0, bl1);
                mma_bf16(acc[ntp][0], acc[ntp][1], acc[ntp][2], acc[ntp][3],
                         al0, al1, al2, al3, bh0, bh1);
                mma_bf16(acc[ntp + 1][0], acc[ntp + 1][1], acc[ntp + 1][2], acc[ntp + 1][3],
                         ah0, ah1, ah2, ah3, bh2, bh3);
                mma_bf16(acc[ntp + 1][0], acc[ntp + 1][1], acc[ntp + 1][2], acc[ntp + 1][3],
                         ah0, ah1, ah2, ah3, bl2, bl3);
                mma_bf16(acc[ntp + 1][0], acc[ntp + 1][1], acc[ntp + 1][2], acc[ntp + 1][3],
                         al0, al1, al2, al3, bh2, bh3);
            }
        }

        // ---- epilogue: bias, mask, exp, write e (fp32), build fp16 PV A-frags ----
        uint32_t efr[8][2];
        #pragma unroll
        for (int nt = 0; nt < 8; nt++) {
            const int gk = k0 + nt * 8 + (lane & 3) * 2;
            const int2 mv = *(const int2*)(maskb + gk);
            float2 bv0 = *(const float2*)(biasb + (long)qr0 * S_ + gk);
            float2 bv1 = *(const float2*)(biasb + (long)qr1 * S_ + gk);
            float l00 = acc[nt][0] + bv0.x; if (mv.x == 0) l00 = NEG_FILL;
            float l01 = acc[nt][1] + bv0.y; if (mv.y == 0) l01 = NEG_FILL;
            float l10 = acc[nt][2] + bv1.x; if (mv.x == 0) l10 = NEG_FILL;
            float l11 = acc[nt][3] + bv1.y; if (mv.y == 0) l11 = NEG_FILL;
            float e00 = __expf(l00), e01 = __expf(l01);
            float e10 = __expf(l10), e11 = __expf(l11);
            sum0 += e00 + e01;
            sum1 += e10 + e11;
            *(float2*)(attb + (long)qr0 * S_ + gk) = make_float2(e00, e01);
            *(float2*)(attb + (long)qr1 * S_ + gk) = make_float2(e10, e11);
            efr[nt][0] = pack_f16(e00 * ESCALE, e01 * ESCALE);   // row g
            efr[nt][1] = pack_f16(e10 * ESCALE, e11 * ESCALE);   // row g+8
        }

        // ---- PV: out[16 x 64] += E[16 x 64] @ V[64 x 64], 1-term fp16 ----
        #pragma unroll
        for (int ks2 = 0; ks2 < 4; ks2++) {
            uint32_t a0 = efr[2 * ks2][0],     a1 = efr[2 * ks2][1];
            uint32_t a2 = efr[2 * ks2 + 1][0], a3 = efr[2 * ks2 + 1][1];
            const uint32_t roff = (uint32_t)(ks2 * 16 * LDT) * 2u;
            #pragma unroll
            for (int dnp = 0; dnp < 8; dnp += 2) {
                uint32_t b0, b1, b2, b3;
                ldsm_x4t(vh_b + roff + dnp * 16u, b0, b1, b2, b3);
                mma_f16(accO[dnp][0], accO[dnp][1], accO[dnp][2], accO[dnp][3],
                        a0, a1, a2, a3, b0, b1);
                mma_f16(accO[dnp + 1][0], accO[dnp + 1][1], accO[dnp + 1][2], accO[dnp + 1][3],
                        a0, a1, a2, a3, b2, b3);
            }
        }
    }

    // ---- row sums: reduce over quad (lanes sharing a row) ----
    sum0 += __shfl_xor_sync(0xffffffffu, sum0, 1);
    sum0 += __shfl_xor_sync(0xffffffffu, sum0, 2);
    sum1 += __shfl_xor_sync(0xffffffffu, sum1, 1);
    sum1 += __shfl_xor_sync(0xffffffffu, sum1, 2);
    const float inv0 = 1.0f / sum0;
    const float inv1 = 1.0f / sum1;
    if ((lane & 3) == 0) {
        row_inv[qr0] = inv0;
        row_inv[qr1] = inv1;
    }

    // ---- write out (normalized; ESCALE_INV undoes the fp16 pre-scale) ----
    #pragma unroll
    for (int dn = 0; dn < 8; dn++) {
        const int dc = dn * 8 + (lane & 3) * 2;
        *(float2*)(out + ((long)bhq * S_ + q0 + qr0) * D_ + dc) =
            make_float2(accO[dn][0] * inv0 * ESCALE_INV, accO[dn][1] * inv0 * ESCALE_INV);
        *(float2*)(out + ((long)bhq * S_ + q0 + qr1) * D_ + dc) =
            make_float2(accO[dn][2] * inv1 * ESCALE_INV, accO[dn][3] * inv1 * ESCALE_INV);
    }

    // ---- fused normalize: scale this block's own 128 attn rows in place ----
    __syncthreads();   // row_inv visible + all e stores visible block-wide
    float4* ab4 = (float4*)attb;          // block's region is contiguous 128*2048 f32
    #pragma unroll 4
    for (int i4 = t; i4 < TQ * S_ / 4; i4 += 256) {
        const float inv = row_inv[i4 >> 9];    // 512 float4 per row
        float4 x = ab4[i4];
        x.x *= inv; x.y *= inv; x.z *= inv; x.w *= inv;
        ab4[i4] = x;
    }
}

extern "C" void kernel_launch(void* const* d_in, const int* in_sizes, int n_in,
                              void* d_out, int out_size) {
    const float* q    = (const float*)d_in[0];
    const float* k    = (const float*)d_in[1];
    const float* v    = (const float*)d_in[2];
    const int*   mask = (const int*)  d_in[3];
    const float* bias = (const float*)d_in[4];

    float* out  = (float*)d_out;
    float* attn = (float*)d_out + (long)B_ * H_ * S_ * D_;

    static int configured = 0;
    if (!configured) {
        cudaFuncSetAttribute(attn_k1,
                             cudaFuncAttributeMaxDynamicSharedMemorySize, SMEM_BYTES);
        configured = 1;
    }

    dim3 grid(S_ / TQ, B_ * H_);        // (16, 24)
    attn_k1<<<grid, 256, SMEM_BYTES>>>(q, k, v, mask, bias, out, attn);
}